// round 1
// baseline (speedup 1.0000x reference)
#include <cuda_runtime.h>

#define TILE    128
#define THREADS 256
#define INF     97     // input features
#define INP     98     // padded input stride (floats)
#define MID     80
#define OUTD    64
#define HSTRIDE 82     // padded H stride (41 doubles, odd -> conflict-free)
#define OSTRIDE 65     // padded output staging stride (odd -> conflict-free stores)

// packed dual-fp32 FMA (sm_100+): 2x throughput vs 3-reg FFMA on sm_103a
__device__ __forceinline__ float2 ffma2(float2 a, float2 b, float2 c) {
    unsigned long long au = *reinterpret_cast<unsigned long long*>(&a);
    unsigned long long bu = *reinterpret_cast<unsigned long long*>(&b);
    unsigned long long cu = *reinterpret_cast<unsigned long long*>(&c);
    asm("fma.rn.f32x2 %0, %1, %2, %0;" : "+l"(cu) : "l"(au), "l"(bu));
    return *reinterpret_cast<float2*>(&cu);
}

// tanh via 2 MUFU ops (EX2 + RCP), ~2^-20 rel error, handles +-inf saturation
__device__ __forceinline__ float fast_tanh(float x) {
    float e = __expf(2.0f * x);                // MUFU.EX2 path
    return 1.0f - __fdividef(2.0f, e + 1.0f);  // MUFU.RCP path
}

extern __shared__ float smem[];

__global__ void __launch_bounds__(THREADS, 1)
edge_mlp_kernel(const float* __restrict__ dstf, const float* __restrict__ dsth,
                const float* __restrict__ srcf, const float* __restrict__ srch,
                const float* __restrict__ ef,
                const float* __restrict__ W1, const float* __restrict__ b1,
                const float* __restrict__ W2, const float* __restrict__ b2,
                float* __restrict__ out, int E)
{
    float* Xs  = smem;                    // TILE*INP floats (reused as output stage)
    float* Hs  = Xs  + TILE * INP;        // TILE*HSTRIDE
    float* W1s = Hs  + TILE * HSTRIDE;    // MID*INP
    float* W2s = W1s + MID * INP;         // OUTD*MID
    float* b1s = W2s + OUTD * MID;        // MID
    float* b2s = b1s + MID;               // OUTD

    const int tid  = threadIdx.x;
    const int lane = tid & 31;
    const int warp = tid >> 5;

    // ---- stage weights once per (persistent) block ----
    for (int i = tid; i < MID * INF; i += THREADS) {
        int m = i / INF, k = i - m * INF;
        W1s[m * INP + k] = W1[i];
    }
    for (int m = tid; m < MID; m += THREADS) W1s[m * INP + INF] = 0.0f; // zero pad col
    for (int i = tid; i < OUTD * MID; i += THREADS) W2s[i] = W2[i];
    for (int i = tid; i < MID;  i += THREADS) b1s[i] = b1[i];
    for (int i = tid; i < OUTD; i += THREADS) b2s[i] = b2[i];
    __syncthreads();

    const int ntiles = (E + TILE - 1) / TILE;

    for (int tile = blockIdx.x; tile < ntiles; tile += gridDim.x) {
        const int e0  = tile * TILE;
        int rem = E - e0; if (rem > TILE) rem = TILE;

        // ---- stage X tile: [dstf(16) | dsth(32) | srcf(16) | srch(32) | edge | 0] ----
        {
            const float2* s0 = (const float2*)(dstf + (size_t)e0 * 16);
            const float2* s1 = (const float2*)(dsth + (size_t)e0 * 32);
            const float2* s2 = (const float2*)(srcf + (size_t)e0 * 16);
            const float2* s3 = (const float2*)(srch + (size_t)e0 * 32);
            float2* X2 = (float2*)Xs;  // row stride 49 (odd) -> conflict-free
            for (int i = tid; i < TILE * 8; i += THREADS) {
                int r = i >> 3, c = i & 7;
                if (r < rem) X2[r * 49 + c] = s0[r * 8 + c];
            }
            for (int i = tid; i < TILE * 16; i += THREADS) {
                int r = i >> 4, c = i & 15;
                if (r < rem) X2[r * 49 + 8 + c] = s1[r * 16 + c];
            }
            for (int i = tid; i < TILE * 8; i += THREADS) {
                int r = i >> 3, c = i & 7;
                if (r < rem) X2[r * 49 + 24 + c] = s2[r * 8 + c];
            }
            for (int i = tid; i < TILE * 16; i += THREADS) {
                int r = i >> 4, c = i & 15;
                if (r < rem) X2[r * 49 + 32 + c] = s3[r * 16 + c];
            }
            for (int r = tid; r < TILE; r += THREADS) {
                Xs[r * INP + 96] = (r < rem) ? ef[e0 + r] : 0.0f;
                Xs[r * INP + 97] = 0.0f;
            }
        }
        __syncthreads();

        // ---- phase A: H = relu(X @ W1^T + b1), warp = 10 m-outputs x all 128 edges ----
        {
            const float2* X2  = (const float2*)Xs;
            const float2* W12 = (const float2*)W1s;  // row stride 49 double units
            const int m0 = warp * 10;
            float2 acc[4][10];
            #pragma unroll
            for (int r = 0; r < 4; r++)
                #pragma unroll
                for (int j = 0; j < 10; j++) acc[r][j] = make_float2(0.f, 0.f);

            for (int kk = 0; kk < 49; ++kk) {
                float2 x0 = X2[(lane      ) * 49 + kk];
                float2 x1 = X2[(lane +  32) * 49 + kk];
                float2 x2 = X2[(lane +  64) * 49 + kk];
                float2 x3 = X2[(lane +  96) * 49 + kk];
                #pragma unroll
                for (int j = 0; j < 10; j++) {
                    float2 w = W12[(m0 + j) * 49 + kk];   // warp-uniform broadcast
                    acc[0][j] = ffma2(x0, w, acc[0][j]);
                    acc[1][j] = ffma2(x1, w, acc[1][j]);
                    acc[2][j] = ffma2(x2, w, acc[2][j]);
                    acc[3][j] = ffma2(x3, w, acc[3][j]);
                }
            }
            #pragma unroll
            for (int j = 0; j < 10; j++) {
                float bb = b1s[m0 + j];
                #pragma unroll
                for (int r = 0; r < 4; r++) {
                    float s = acc[r][j].x + acc[r][j].y + bb;
                    Hs[(lane + r * 32) * HSTRIDE + m0 + j] = fmaxf(s, 0.0f);
                }
            }
        }
        __syncthreads();

        // ---- phase B: O = tanh(H @ W2^T + b2), warp = 8 o-outputs x all 128 edges ----
        {
            const float2* H2  = (const float2*)Hs;   // row stride 41 (odd)
            const float2* W22 = (const float2*)W2s;  // row stride 40
            float* Ot = Xs;                          // reuse X buffer as staging
            const int o0 = warp * 8;
            float2 acc[4][8];
            #pragma unroll
            for (int r = 0; r < 4; r++)
                #pragma unroll
                for (int j = 0; j < 8; j++) acc[r][j] = make_float2(0.f, 0.f);

            for (int kk = 0; kk < 40; ++kk) {
                float2 h0 = H2[(lane      ) * 41 + kk];
                float2 h1 = H2[(lane +  32) * 41 + kk];
                float2 h2 = H2[(lane +  64) * 41 + kk];
                float2 h3 = H2[(lane +  96) * 41 + kk];
                #pragma unroll
                for (int j = 0; j < 8; j++) {
                    float2 w = W22[(o0 + j) * 40 + kk];   // warp-uniform broadcast
                    acc[0][j] = ffma2(h0, w, acc[0][j]);
                    acc[1][j] = ffma2(h1, w, acc[1][j]);
                    acc[2][j] = ffma2(h2, w, acc[2][j]);
                    acc[3][j] = ffma2(h3, w, acc[3][j]);
                }
            }
            #pragma unroll
            for (int j = 0; j < 8; j++) {
                float bb = b2s[o0 + j];
                #pragma unroll
                for (int r = 0; r < 4; r++) {
                    float s = acc[r][j].x + acc[r][j].y + bb;
                    Ot[(lane + r * 32) * OSTRIDE + o0 + j] = fast_tanh(s);
                }
            }
        }
        __syncthreads();

        // ---- coalesced write-out ----
        {
            float* outp = out + (size_t)e0 * OUTD;
            for (int i = tid; i < TILE * OUTD; i += THREADS) {
                int r = i >> 6, c = i & 63;
                if (r < rem) outp[i] = Xs[r * OSTRIDE + c];
            }
        }
        __syncthreads();  // protect Xs before next tile's staging
    }
}

extern "C" void kernel_launch(void* const* d_in, const int* in_sizes, int n_in,
                              void* d_out, int out_size) {
    const float* dstf = (const float*)d_in[0];
    const float* dsth = (const float*)d_in[1];
    const float* srcf = (const float*)d_in[2];
    const float* srch = (const float*)d_in[3];
    const float* ef   = (const float*)d_in[4];
    const float* W1   = (const float*)d_in[5];
    const float* b1   = (const float*)d_in[6];
    const float* W2   = (const float*)d_in[7];
    const float* b2   = (const float*)d_in[8];
    float* out = (float*)d_out;
    const int E = in_sizes[4];   // edge_feat element count = number of edges
    (void)n_in; (void)out_size;

    const int smem_bytes = (TILE * INP + TILE * HSTRIDE + MID * INP +
                            OUTD * MID + MID + OUTD) * (int)sizeof(float);  // 144,576 B

    cudaFuncSetAttribute(edge_mlp_kernel,
                         cudaFuncAttributeMaxDynamicSharedMemorySize, smem_bytes);

    int sms = 148;
    cudaDeviceGetAttribute(&sms, cudaDevAttrMultiProcessorCount, 0);

    edge_mlp_kernel<<<sms, THREADS, smem_bytes>>>(
        dstf, dsth, srcf, srch, ef, W1, b1, W2, b2, out, E);
}